// round 13
// baseline (speedup 1.0000x reference)
#include <cuda_runtime.h>
#include <cstdint>

#define NF          64
#define XR4         16                 // float4 per x row
#define TILE        128
#define SLOTS       3
#define SMEM_BYTES  (SLOTS * TILE * NF * 4)   // 98304
#define THREADS     256
#define GROUP_ROWS  32
#define N_TILES     2048               // 262144 / 128
#define GRID        296                // 148 SMs x 2 blocks
#define BIG         272                // blocks that take 7 tiles (272*7 + 24*6 = 2048)

__global__ void __launch_bounds__(THREADS, 2)
ma_kernel(const float* __restrict__ x, float* __restrict__ out) {
    extern __shared__ float4 sm4[];
    float* sm = (float*)sm4;                   // ring: [SLOTS*TILE][NF]

    const int t   = threadIdx.x;
    const int blk = blockIdx.x;

    int start, len;
    if (blk < BIG) { start = blk * 7;                len = 7; }
    else           { start = BIG * 7 + (blk - BIG) * 6; len = 6; }
    const int end = start + len;

    const float4* x4 = (const float4*)x;

    // ---- Prologue: halo (last 90 rows of tile start-1) into slot (start-1)%3 ----
    {
        int pslot = (start + SLOTS - 1) % SLOTS;
        if (start == 0) {
            for (int idx = t; idx < 90 * XR4; idx += THREADS)
                sm4[(pslot * TILE + 38) * XR4 + idx] = make_float4(0.f, 0.f, 0.f, 0.f);
        } else {
            uint32_t sdst = (uint32_t)__cvta_generic_to_shared(sm4 + (pslot * TILE + 38) * XR4);
            const float4* src = x4 + ((size_t)start * TILE - 90) * XR4;
            for (int idx = t; idx < 90 * XR4; idx += THREADS)
                asm volatile("cp.async.cg.shared.global [%0], [%1], 16;" ::
                             "r"(sdst + (uint32_t)idx * 16u), "l"(src + idx));
        }
        // prefetch tile start (same group as halo) and tile start+1
        for (int pk = start; pk <= start + 1; pk++) {
            int slot = pk % SLOTS;
            uint32_t sdst = (uint32_t)__cvta_generic_to_shared(sm4 + slot * TILE * XR4);
            const float4* src = x4 + (size_t)pk * TILE * XR4;
            #pragma unroll
            for (int i = 0; i < (TILE * XR4) / THREADS; i++) {    // 8
                int idx = t + i * THREADS;
                asm volatile("cp.async.cg.shared.global [%0], [%1], 16;" ::
                             "r"(sdst + (uint32_t)idx * 16u), "l"(src + idx));
            }
            asm volatile("cp.async.commit_group;");
        }
    }

    const int c   = t & (NF - 1);              // column 0..63
    const int g   = t >> 6;                    // group 0..3
    const int off = g * GROUP_ROWS;            // row offset within tile
    const float inv7  = 1.0f / 7.0f;
    const float inv30 = 1.0f / 30.0f;
    const float inv90 = 1.0f / 90.0f;

    for (int k = start; k < end; k++) {
        if (k + 1 < end) asm volatile("cp.async.wait_group 1;");
        else             asm volatile("cp.async.wait_group 0;");
        __syncthreads();

        const int tc  = k % SLOTS;             // slot of current tile
        const int sp  = (tc + SLOTS - 1) % SLOTS;
        const int gr0 = k * TILE + off;        // first global row of my strip

        float s7 = 0.f, s30 = 0.f, s90 = 0.f;

        // Warm-up: 90 rows preceding the strip (ring addressing, <=1 wrap).
        {
            const int bc = tc * TILE + off;        // ring row of gr0
            const int bp = sp * TILE + TILE + off; // bp - kk for rows in prev tile
            #pragma unroll 10
            for (int kk = 1; kk <= 90; kk++) {
                int row = (kk <= off) ? (bc - kk) : (bp - kk);
                float v = sm[row * NF + c];
                s90 += v;
                if (kk <= 30) s30 += v;
                if (kk <= 7)  s7  += v;
            }
        }

        // Lag base rows (ring). Only lag-90 of group 2 crosses a slot boundary.
        const int bv  = tc * TILE + off;
        const int b7  = (off >= 7)  ? (bv - 7)  : (sp * TILE + 121 + off);
        const int b30 = (off >= 30) ? (bv - 30) : (sp * TILE + 98 + off);
        int jw, b90lo, b90hi;
        if (off >= 90) { jw = GROUP_ROWS * 2; b90lo = bv - 90; b90hi = 0; }
        else {
            jw = 90 - off;                       // split point (>=32 means no split)
            b90lo = sp * TILE + 38 + off;
            b90hi = tc * TILE - jw;
        }

        float* oc = out + c;
        float hist[GROUP_ROWS];

        if (gr0 < 90) {
            // Careful region (chain start==0, tile 0, groups 0..2 only).
            #pragma unroll
            for (int j = 0; j < GROUP_ROWS; j++) {
                float v = sm[(bv + j) * NF + c]; hist[j] = v;
                float v7  = (j >= 7)  ? hist[j - 7]  : sm[(b7 + j) * NF + c];
                float v30 = (j >= 30) ? hist[j - 30] : sm[(b30 + j) * NF + c];
                float v90 = sm[(((j < jw) ? b90lo : b90hi) + j) * NF + c];
                s7 += v - v7; s30 += v - v30; s90 += v - v90;
                int gi = gr0 + j;
                float rn  = 1.0f / (float)(gi + 1);
                float r7  = (gi >= 6)  ? inv7  : rn;
                float r30 = (gi >= 29) ? inv30 : rn;
                float r90 = (gi >= 89) ? inv90 : rn;
                float* o = oc + (size_t)gi * (4 * NF);
                __stcs(o,          v);
                __stcs(o + NF,     s7  * r7);
                __stcs(o + 2 * NF, s30 * r30);
                __stcs(o + 3 * NF, s90 * r90);
            }
        } else {
            #pragma unroll
            for (int j = 0; j < GROUP_ROWS; j++) {
                float v = sm[(bv + j) * NF + c]; hist[j] = v;
                float v7  = (j >= 7)  ? hist[j - 7]  : sm[(b7 + j) * NF + c];
                float v30 = (j >= 30) ? hist[j - 30] : sm[(b30 + j) * NF + c];
                float v90 = sm[(((j < jw) ? b90lo : b90hi) + j) * NF + c];
                s7 += v - v7; s30 += v - v30; s90 += v - v90;
                float* o = oc + (size_t)(gr0 + j) * (4 * NF);
                __stcs(o,          v);
                __stcs(o + NF,     s7  * inv7);
                __stcs(o + 2 * NF, s30 * inv30);
                __stcs(o + 3 * NF, s90 * inv90);
            }
        }

        __syncthreads();   // all readers done with slot (k-1)%3 before overwrite

        if (k + 2 < end) {
            int slot = (k + 2) % SLOTS;
            uint32_t sdst = (uint32_t)__cvta_generic_to_shared(sm4 + slot * TILE * XR4);
            const float4* src = x4 + (size_t)(k + 2) * TILE * XR4;
            #pragma unroll
            for (int i = 0; i < (TILE * XR4) / THREADS; i++) {
                int idx = t + i * THREADS;
                asm volatile("cp.async.cg.shared.global [%0], [%1], 16;" ::
                             "r"(sdst + (uint32_t)idx * 16u), "l"(src + idx));
            }
            asm volatile("cp.async.commit_group;");
        }
    }
}

extern "C" void kernel_launch(void* const* d_in, const int* in_sizes, int n_in,
                              void* d_out, int out_size) {
    const float* x  = (const float*)d_in[0];
    float*      out = (float*)d_out;
    static int attr_set = 0;
    if (!attr_set) {
        cudaFuncSetAttribute(ma_kernel,
                             cudaFuncAttributeMaxDynamicSharedMemorySize,
                             SMEM_BYTES);
        attr_set = 1;
    }
    ma_kernel<<<GRID, THREADS, SMEM_BYTES>>>(x, out);
}

// round 15
// speedup vs baseline: 1.0980x; 1.0980x over previous
#include <cuda_runtime.h>
#include <cstdint>

#define T_TOTAL    262144
#define NF         64
#define NP         32                  // float2 pairs per x row
#define ONP        128                 // float2 pairs per out row
#define XR4        16                  // float4 per x row
#define TILE_ROWS  256
#define HALO       90
#define SROWS      (TILE_ROWS + HALO)  // 346
#define SMEM_F4    (SROWS * XR4)       // 5536
#define SMEM_BYTES (SMEM_F4 * 16)      // 88576
#define THREADS    256
#define GROUPS     8
#define GROUP_ROWS (TILE_ROWS / GROUPS)  // 32

__device__ __forceinline__ float2 f2add(float2 a, float2 b) {
    return make_float2(a.x + b.x, a.y + b.y);
}
__device__ __forceinline__ float2 f2sub(float2 a, float2 b) {
    return make_float2(a.x - b.x, a.y - b.y);
}
__device__ __forceinline__ float2 f2scale(float2 a, float s) {
    return make_float2(a.x * s, a.y * s);
}

__global__ void __launch_bounds__(THREADS, 2)
ma_kernel(const float* __restrict__ x, float* __restrict__ out) {
    extern __shared__ float4 sm4[];
    float2* sm2 = (float2*)sm4;                 // [SROWS][NP]

    const int t    = threadIdx.x;
    const int blk  = blockIdx.x;
    const int base = blk * TILE_ROWS - HALO;    // global row of smem row 0

    // ---- Phase 1: cp.async stream tile + halo into smem ----
    const int pad = (blk == 0) ? HALO : 0;      // rows < 0 are implicit zeros
    if (pad) {
        for (int idx = t; idx < pad * XR4; idx += THREADS)
            sm4[idx] = make_float4(0.f, 0.f, 0.f, 0.f);
    }
    {
        uint32_t sdst = (uint32_t)__cvta_generic_to_shared(sm4 + pad * XR4);
        const float4* src = (const float4*)x + (base + pad) * XR4;
        const int n4 = (SROWS - pad) * XR4;
        #pragma unroll 5
        for (int idx = t; idx < n4; idx += THREADS) {
            asm volatile("cp.async.cg.shared.global [%0], [%1], 16;" ::
                         "r"(sdst + (uint32_t)idx * 16u), "l"(src + idx));
        }
        asm volatile("cp.async.commit_group;");
        asm volatile("cp.async.wait_group 0;");
    }
    __syncthreads();

    // ---- Phase 2: one column-pair per thread, 32-row strip per group ----
    const int p   = t & (NP - 1);               // column pair 0..31
    const int g   = t >> 5;                     // group 0..7
    const int lr0 = HALO + g * GROUP_ROWS;      // first smem row of strip
    const int gr0 = blk * TILE_ROWS + g * GROUP_ROWS;

    float2 s7  = make_float2(0.f, 0.f);
    float2 s30 = s7, s90 = s7;

    // Entry sums over the 90 rows preceding the strip (zero-padded for blk 0).
    #pragma unroll 10
    for (int k = 1; k <= HALO; k++) {
        float2 v = sm2[(lr0 - k) * NP + p];
        s90 = f2add(s90, v);
        if (k <= 30) s30 = f2add(s30, v);
        if (k <= 7)  s7  = f2add(s7, v);
    }

    const float inv7  = 1.0f / 7.0f;
    const float inv30 = 1.0f / 30.0f;
    const float inv90 = 1.0f / 90.0f;

    float2* oc = (float2*)out + p;              // row stride ONP

    if (gr0 < 90) {
        // Careful region (blk 0, groups 0..2): expanding divisors; zero-padded
        // halo makes the sliding sums equal the cumsum automatically.
        #pragma unroll
        for (int j = 0; j < GROUP_ROWS; j++) {
            int lr = lr0 + j;
            int gi = gr0 + j;
            float2 v   = sm2[lr * NP + p];
            float2 v7  = sm2[(lr - 7)  * NP + p];
            float2 v30 = sm2[(lr - 30) * NP + p];
            float2 v90 = sm2[(lr - 90) * NP + p];
            s7  = f2add(s7,  f2sub(v, v7));
            s30 = f2add(s30, f2sub(v, v30));
            s90 = f2add(s90, f2sub(v, v90));
            float rn  = 1.0f / (float)(gi + 1);
            float r7  = (gi >= 6)  ? inv7  : rn;
            float r30 = (gi >= 29) ? inv30 : rn;
            float r90 = (gi >= 89) ? inv90 : rn;
            float2* o = oc + (size_t)gi * ONP;
            __stcs(o,          v);
            __stcs(o + NP,     f2scale(s7,  r7));
            __stcs(o + 2 * NP, f2scale(s30, r30));
            __stcs(o + 3 * NP, f2scale(s90, r90));
        }
    } else {
        #pragma unroll
        for (int j = 0; j < GROUP_ROWS; j++) {
            int lr = lr0 + j;
            int gi = gr0 + j;
            float2 v   = sm2[lr * NP + p];
            float2 v7  = sm2[(lr - 7)  * NP + p];
            float2 v30 = sm2[(lr - 30) * NP + p];
            float2 v90 = sm2[(lr - 90) * NP + p];
            s7  = f2add(s7,  f2sub(v, v7));
            s30 = f2add(s30, f2sub(v, v30));
            s90 = f2add(s90, f2sub(v, v90));
            float2* o = oc + (size_t)gi * ONP;
            __stcs(o,          v);
            __stcs(o + NP,     f2scale(s7,  inv7));
            __stcs(o + 2 * NP, f2scale(s30, inv30));
            __stcs(o + 3 * NP, f2scale(s90, inv90));
        }
    }
}

extern "C" void kernel_launch(void* const* d_in, const int* in_sizes, int n_in,
                              void* d_out, int out_size) {
    const float* x  = (const float*)d_in[0];
    float*      out = (float*)d_out;
    static int attr_set = 0;
    if (!attr_set) {
        cudaFuncSetAttribute(ma_kernel,
                             cudaFuncAttributeMaxDynamicSharedMemorySize,
                             SMEM_BYTES);
        attr_set = 1;
    }
    int n_blocks = T_TOTAL / TILE_ROWS;         // 1024
    ma_kernel<<<n_blocks, THREADS, SMEM_BYTES>>>(x, out);
}